// round 12
// baseline (speedup 1.0000x reference)
#include <cuda_runtime.h>
#include <cuda_bf16.h>
#include <cstdint>

#define DEV_INLINE __device__ __forceinline__

constexpr int Bb = 8;
constexpr int Nn = 4096;

// ---------------- static device scratch (no allocation) ----------------
__device__ float    g_h32[Bb * Nn * 64];          // h fp32 (8 MB)
__device__ unsigned g_hpk_hi[Bb * (Nn/2) * 64];   // h bf16, node-pair packed (4 MB)

DEV_INLINE unsigned packbf(float a, float b) {
    __nv_bfloat162 t2 = __floats2bfloat162_rn(a, b);
    return *reinterpret_cast<unsigned*>(&t2);
}

DEV_INLINE void mma_bf16(float* c, const unsigned* a, const unsigned* b) {
    asm volatile(
        "mma.sync.aligned.m16n8k16.row.col.f32.bf16.bf16.f32 "
        "{%0,%1,%2,%3}, {%4,%5,%6,%7}, {%8,%9}, {%0,%1,%2,%3};\n"
        : "+f"(c[0]), "+f"(c[1]), "+f"(c[2]), "+f"(c[3])
        : "r"(a[0]), "r"(a[1]), "r"(a[2]), "r"(a[3]), "r"(b[0]), "r"(b[1]));
}

DEV_INLINE void ldsm4(unsigned* r, uint32_t addr) {
    asm volatile(
        "ldmatrix.sync.aligned.m8n8.x4.shared.b16 {%0,%1,%2,%3}, [%4];\n"
        : "=r"(r[0]), "=r"(r[1]), "=r"(r[2]), "=r"(r[3]) : "r"(addr));
}

// ============================================================================
// Kernel 1 (mma): h[64-node tile, 64] = x_tile[64,128] @ W[128,64].
// 128 thr / 4 warps, warp = 16 rows. A stride-68, B stride-72 (R2-proven
// fragment layouts). acc staged through smem for pair packing + fp32 out.
// ============================================================================
constexpr int K1_OFFW = 64 * 68;                // after x tile
constexpr int K1_U32  = K1_OFFW + 64 * 72;      // 8960 u32 = 35.8 KB

__global__ void __launch_bounds__(128)
spconv_h_mma(const float* __restrict__ x, const float* __restrict__ wgt)
{
    __shared__ unsigned sm1[K1_U32];
    const uint32_t smb = (uint32_t)__cvta_generic_to_shared(sm1);
    const int t = threadIdx.x;
    const int lane = t & 31, warp = t >> 5;
    const int g = lane >> 2, tg = lane & 3;
    const int lm_row = lane & 15, lm_kp = ((lane >> 4) & 1) * 4;
    const int b = blockIdx.y;
    const int node0 = blockIdx.x * 64;

    // ---- load x tile -> bf16 pairs (row-major, stride 68 u32) ----
    {
        const int row = t >> 1, hc = t & 1;
        const float* src = x + ((size_t)(b * Nn) + node0 + row) * 128 + hc * 64;
        unsigned* dst = sm1 + row * 68 + hc * 32;
#pragma unroll
        for (int i = 0; i < 16; i++) {
            float4 v = ((const float4*)src)[i];
            dst[2*i]   = packbf(v.x, v.y);
            dst[2*i+1] = packbf(v.z, v.w);
        }
    }
    // ---- load W -> bf16 kpair layout (stride 72 u32) ----
    for (int idx = t; idx < 64 * 64; idx += 128) {
        int kp = idx >> 6, j = idx & 63;
        int ka = kp * 2, m = ka >> 5, a = ka & 31, p = j >> 4, w = j & 15;
        const float* wp = wgt + (((m * 4 + p) * 32 + a) << 4) + w;
        sm1[K1_OFFW + kp * 72 + j] = packbf(wp[0], wp[16]);  // a, a+1
    }
    __syncthreads();

    // ---- mma: warp rows 16*warp..+15, full 64 cols, K=128 ----
    float acc[8][4];
#pragma unroll
    for (int nf = 0; nf < 8; nf++)
#pragma unroll
        for (int i = 0; i < 4; i++) acc[nf][i] = 0.f;

    const uint32_t aBase = smb + ((warp * 16 + lm_row) * 68) * 4;
#pragma unroll
    for (int ks = 0; ks < 8; ks++) {
        unsigned ah[4];
        ldsm4(ah, aBase + (ks * 8 + lm_kp) * 4);
#pragma unroll
        for (int nf = 0; nf < 8; nf++) {
            unsigned bh[2];
            bh[0] = sm1[K1_OFFW + (ks * 8 + tg) * 72 + nf * 8 + g];
            bh[1] = sm1[K1_OFFW + (ks * 8 + 4 + tg) * 72 + nf * 8 + g];
            mma_bf16(acc[nf], ah, bh);
        }
    }
    __syncthreads();                 // x tile no longer needed; reuse as hbuf

    // ---- stage acc -> hbuf[64][65] fp32 ----
    float* hb = (float*)sm1;
    {
        const int r = warp * 16 + g;
#pragma unroll
        for (int nf = 0; nf < 8; nf++) {
            int c = nf * 8 + 2 * tg;
            hb[r * 65 + c]           = acc[nf][0];
            hb[r * 65 + c + 1]       = acc[nf][1];
            hb[(r + 8) * 65 + c]     = acc[nf][2];
            hb[(r + 8) * 65 + c + 1] = acc[nf][3];
        }
    }
    __syncthreads();

    // ---- emit fp32 h ----
    {
        const int r = t >> 1, hc = (t & 1) * 32;
        float* op = g_h32 + ((size_t)(b * Nn) + node0 + r) * 64 + hc;
#pragma unroll
        for (int i = 0; i < 8; i++) {
            const float* s = hb + r * 65 + hc + i * 4;
            *(float4*)(op + i * 4) = make_float4(s[0], s[1], s[2], s[3]);
        }
    }
    // ---- emit node-pair packed bf16 ----
#pragma unroll
    for (int q = 0; q < 16; q++) {
        int idx = t + q * 128;               // 0..2047
        int pr = idx >> 6, j = idx & 63;
        float v0 = hb[(2 * pr) * 65 + j];
        float v1 = hb[(2 * pr + 1) * 65 + j];
        g_hpk_hi[(size_t)b * 131072 + ((node0 >> 1) + pr) * 64 + j] = packbf(v0, v1);
    }
}

// ============================================================================
// Kernel 2: R11 compute loop verbatim; cp.async now fetches 4 k-tiles per
// group (512B contiguous per adj row per visit). 2 super-stages, 2 CTAs/SM.
// ============================================================================
constexpr int AF_STR  = 136;                   // floats per A row (128 + 8 pad)
constexpr int A_SUPER = 64 * AF_STR;           // 8704 u32
constexpr int B_STR   = 72;
constexpr int B_TILE  = 16 * B_STR;            // 1152 u32
constexpr int B_SUPER = 4 * B_TILE;            // 4608 u32
constexpr int OFF_A  = 0;                              // 2 supers
constexpr int OFF_B  = 2 * A_SUPER;                    // 17408
constexpr int OFF_RS = OFF_B + 2 * B_SUPER;            // 26624
constexpr int OFF_RI = OFF_RS + 64;                    // 26688
constexpr int SMEM_U32 = OFF_RI + 64;                  // 26752
constexpr int SMEM_BYTES = SMEM_U32 * 4;               // 107008

DEV_INLINE void cp16(uint32_t saddr, const void* gptr) {
    asm volatile("cp.async.cg.shared.global [%0], [%1], 16;\n"
                 :: "r"(saddr), "l"(gptr));
}
DEV_INLINE void cp_commit() { asm volatile("cp.async.commit_group;\n"); }
DEV_INLINE void cp_wait1()  { asm volatile("cp.async.wait_group 1;\n"); }
DEV_INLINE void cp_wait0()  { asm volatile("cp.async.wait_group 0;\n"); }

__global__ void __launch_bounds__(256, 2)
spconv_gemm_kernel(const float* __restrict__ adj, const float* __restrict__ bias,
                   float* __restrict__ out)
{
    extern __shared__ unsigned sm[];
    const uint32_t smb = (uint32_t)__cvta_generic_to_shared(sm);

    const int t    = threadIdx.x;
    const int lane = t & 31, warp = t >> 5;
    const int g = lane >> 2, tg = lane & 3;
    const int wrow = warp >> 1, wcol = warp & 1;     // 4 x 2 warp grid
    const int bx = blockIdx.x, b = blockIdx.y;

    // A copy: row = t>>2, 128B chunk (t&3)*32 floats; quad covers 512B/row
    const int arow = t >> 2, aq = t & 3;
    const float* adj_base =
        adj + ((size_t)(b * Nn) + (size_t)bx * 64 + arow) * Nn + aq * 32;
    const uint32_t sa_base = smb + (OFF_A + arow * AF_STR + aq * 32) * 4;
    // B copy: per tile, kpair = t>>4, 16B chunk (t&15)*4 u32
    const int bkp = t >> 4, bn4 = (t & 15) * 4;
    const unsigned* hpH = g_hpk_hi + (size_t)b * 131072 + bkp * 64 + bn4;
    const uint32_t sb_base = smb + (OFF_B + bkp * B_STR + bn4) * 4;

    float acc[4][4];
#pragma unroll
    for (int nf = 0; nf < 4; nf++)
#pragma unroll
        for (int i = 0; i < 4; i++) acc[nf][i] = 0.f;

    float rsum0 = 0.f, rsum1 = 0.f;
    const int r0 = wrow * 16 + g;

    auto issue = [&](int ktg, int s) {
        const float* ga = adj_base + (size_t)ktg * 128;
        uint32_t sa = sa_base + s * (A_SUPER * 4);
#pragma unroll
        for (int i = 0; i < 8; i++)
            cp16(sa + i * 16, ga + i * 4);
        uint32_t sb = sb_base + s * (B_SUPER * 4);
        const unsigned* gb = hpH + (size_t)ktg * 4096;
#pragma unroll
        for (int q = 0; q < 4; q++)
            cp16(sb + q * (B_TILE * 4), gb + q * 1024);
        cp_commit();
    };

    auto compute = [&](int s, int sub) {
        const float*    Af = (const float*)(sm + OFF_A + s * A_SUPER);
        const unsigned* Bh = sm + OFF_B + s * B_SUPER + sub * B_TILE;
#pragma unroll
        for (int ks = 0; ks < 2; ks++) {
            unsigned bh[4][2];
#pragma unroll
            for (int nf = 0; nf < 4; nf++) {
                int n = wcol * 32 + nf * 8 + g;
                int k0 = (ks * 8 + tg) * B_STR + n;
                bh[nf][0] = Bh[k0];  bh[nf][1] = Bh[k0 + 4 * B_STR];
            }
            const int kb = sub * 32 + ks * 16 + 2 * tg;
            float2 p0 = *(const float2*)(Af + (r0    ) * AF_STR + kb);
            float2 p1 = *(const float2*)(Af + (r0 + 8) * AF_STR + kb);
            float2 p2 = *(const float2*)(Af + (r0    ) * AF_STR + kb + 8);
            float2 p3 = *(const float2*)(Af + (r0 + 8) * AF_STR + kb + 8);
            if (wcol == 0) {
                rsum0 += (p0.x + p0.y) + (p2.x + p2.y);
                rsum1 += (p1.x + p1.y) + (p3.x + p3.y);
            }
            unsigned ah[4];
            ah[0] = packbf(p0.x, p0.y); ah[1] = packbf(p1.x, p1.y);
            ah[2] = packbf(p2.x, p2.y); ah[3] = packbf(p3.x, p3.y);
#pragma unroll
            for (int nf = 0; nf < 4; nf++)
                mma_bf16(acc[nf], ah, bh[nf]);
        }
    };

    // ---- super-tile pipeline: 32 supers of 4 k-tiles each ----
    issue(0, 0);
    issue(1, 1);
#pragma unroll 1
    for (int ktg = 0; ktg < 32; ktg++) {
        const int s = ktg & 1;
        if (ktg == 31) cp_wait0(); else cp_wait1();
        __syncthreads();
#pragma unroll
        for (int sub = 0; sub < 4; sub++)
            compute(s, sub);
        __syncthreads();
        if (ktg <= 29) issue(ktg + 2, s);
    }

    // ---- rowsum -> rinv ----
    float* rs   = (float*)(sm + OFF_RS);
    float* rinv = (float*)(sm + OFF_RI);
    __syncthreads();
    if (wcol == 0) {
        rsum0 += __shfl_xor_sync(0xffffffffu, rsum0, 1);
        rsum0 += __shfl_xor_sync(0xffffffffu, rsum0, 2);
        rsum1 += __shfl_xor_sync(0xffffffffu, rsum1, 1);
        rsum1 += __shfl_xor_sync(0xffffffffu, rsum1, 2);
        if (tg == 0) { rs[r0] = rsum0; rs[r0 + 8] = rsum1; }
    }
    __syncthreads();
    if (t < 64) rinv[t] = 1.0f / (1.0f + rs[t]);   // +1 = self loop
    __syncthreads();

    // ---- epilogue: out = relu((S + h)*rinv) + bias ----
#pragma unroll
    for (int nf = 0; nf < 4; nf++) {
        int c  = wcol * 32 + nf * 8 + 2 * tg;
        float ri0 = rinv[r0], ri1 = rinv[r0 + 8];
        int gr0 = bx * 64 + r0;
        size_t o0 = ((size_t)(b * Nn + gr0)) * 64 + c;
        size_t o1 = o0 + (size_t)8 * 64;
        float2 h0 = *(const float2*)(g_h32 + o0);
        float2 h1 = *(const float2*)(g_h32 + o1);
        float bz0 = __ldg(bias + c), bz1 = __ldg(bias + c + 1);
        float2 w0, w1;
        w0.x = fmaxf((acc[nf][0] + h0.x) * ri0, 0.f) + bz0;
        w0.y = fmaxf((acc[nf][1] + h0.y) * ri0, 0.f) + bz1;
        w1.x = fmaxf((acc[nf][2] + h1.x) * ri1, 0.f) + bz0;
        w1.y = fmaxf((acc[nf][3] + h1.y) * ri1, 0.f) + bz1;
        *(float2*)(out + o0) = w0;
        *(float2*)(out + o1) = w1;
    }
}

// ============================================================================
extern "C" void kernel_launch(void* const* d_in, const int* in_sizes, int n_in,
                              void* d_out, int out_size)
{
    const float* x    = (const float*)d_in[0];
    const float* adj  = (const float*)d_in[1];
    const float* wgt  = (const float*)d_in[2];
    const float* bias = (const float*)d_in[3];
    float* out = (float*)d_out;

    cudaFuncSetAttribute(spconv_gemm_kernel,
                         cudaFuncAttributeMaxDynamicSharedMemorySize, SMEM_BYTES);

    spconv_h_mma<<<dim3(64, 8), 128>>>(x, wgt);
    spconv_gemm_kernel<<<dim3(64, 8), 256, SMEM_BYTES>>>(adj, bias, out);
}

// round 13
// speedup vs baseline: 1.4639x; 1.4639x over previous
#include <cuda_runtime.h>
#include <cuda_bf16.h>
#include <cstdint>

#define DEV_INLINE __device__ __forceinline__

constexpr int Bb = 8;
constexpr int Nn = 4096;

// ---------------- static device scratch (no allocation) ----------------
__device__ float    g_h32[Bb * Nn * 64];          // h fp32 (8 MB)
__device__ unsigned g_hpk_hi[Bb * (Nn/2) * 64];   // h bf16, node-pair packed (4 MB)

DEV_INLINE unsigned packbf(float a, float b) {
    __nv_bfloat162 t2 = __floats2bfloat162_rn(a, b);
    return *reinterpret_cast<unsigned*>(&t2);
}

DEV_INLINE void mma_bf16(float* c, const unsigned* a, const unsigned* b) {
    asm volatile(
        "mma.sync.aligned.m16n8k16.row.col.f32.bf16.bf16.f32 "
        "{%0,%1,%2,%3}, {%4,%5,%6,%7}, {%8,%9}, {%0,%1,%2,%3};\n"
        : "+f"(c[0]), "+f"(c[1]), "+f"(c[2]), "+f"(c[3])
        : "r"(a[0]), "r"(a[1]), "r"(a[2]), "r"(a[3]), "r"(b[0]), "r"(b[1]));
}

DEV_INLINE void ldsm4(unsigned* r, uint32_t addr) {
    asm volatile(
        "ldmatrix.sync.aligned.m8n8.x4.shared.b16 {%0,%1,%2,%3}, [%4];\n"
        : "=r"(r[0]), "=r"(r[1]), "=r"(r[2]), "=r"(r[3]) : "r"(addr));
}

// ============================================================================
// Kernel 1 (mma, from R12): h[64-node tile, 64] = x_tile[64,128] @ W[128,64].
// ============================================================================
constexpr int K1_OFFW = 64 * 68;                // after x tile
constexpr int K1_U32  = K1_OFFW + 64 * 72;      // 8960 u32 = 35.8 KB

__global__ void __launch_bounds__(128)
spconv_h_mma(const float* __restrict__ x, const float* __restrict__ wgt)
{
    __shared__ unsigned sm1[K1_U32];
    const uint32_t smb = (uint32_t)__cvta_generic_to_shared(sm1);
    const int t = threadIdx.x;
    const int lane = t & 31, warp = t >> 5;
    const int g = lane >> 2, tg = lane & 3;
    const int lm_row = lane & 15, lm_kp = ((lane >> 4) & 1) * 4;
    const int b = blockIdx.y;
    const int node0 = blockIdx.x * 64;

    // ---- load x tile -> bf16 pairs (row-major, stride 68 u32) ----
    {
        const int row = t >> 1, hc = t & 1;
        const float* src = x + ((size_t)(b * Nn) + node0 + row) * 128 + hc * 64;
        unsigned* dst = sm1 + row * 68 + hc * 32;
#pragma unroll
        for (int i = 0; i < 16; i++) {
            float4 v = ((const float4*)src)[i];
            dst[2*i]   = packbf(v.x, v.y);
            dst[2*i+1] = packbf(v.z, v.w);
        }
    }
    // ---- load W -> bf16 kpair layout (stride 72 u32) ----
    for (int idx = t; idx < 64 * 64; idx += 128) {
        int kp = idx >> 6, j = idx & 63;
        int ka = kp * 2, m = ka >> 5, a = ka & 31, p = j >> 4, w = j & 15;
        const float* wp = wgt + (((m * 4 + p) * 32 + a) << 4) + w;
        sm1[K1_OFFW + kp * 72 + j] = packbf(wp[0], wp[16]);  // a, a+1
    }
    __syncthreads();

    // ---- mma: warp rows 16*warp..+15, full 64 cols, K=128 ----
    float acc[8][4];
#pragma unroll
    for (int nf = 0; nf < 8; nf++)
#pragma unroll
        for (int i = 0; i < 4; i++) acc[nf][i] = 0.f;

    const uint32_t aBase = smb + ((warp * 16 + lm_row) * 68) * 4;
#pragma unroll
    for (int ks = 0; ks < 8; ks++) {
        unsigned ah[4];
        ldsm4(ah, aBase + (ks * 8 + lm_kp) * 4);
#pragma unroll
        for (int nf = 0; nf < 8; nf++) {
            unsigned bh[2];
            bh[0] = sm1[K1_OFFW + (ks * 8 + tg) * 72 + nf * 8 + g];
            bh[1] = sm1[K1_OFFW + (ks * 8 + 4 + tg) * 72 + nf * 8 + g];
            mma_bf16(acc[nf], ah, bh);
        }
    }
    __syncthreads();                 // x tile no longer needed; reuse as hbuf

    // ---- stage acc -> hbuf[64][65] fp32 ----
    float* hb = (float*)sm1;
    {
        const int r = warp * 16 + g;
#pragma unroll
        for (int nf = 0; nf < 8; nf++) {
            int c = nf * 8 + 2 * tg;
            hb[r * 65 + c]           = acc[nf][0];
            hb[r * 65 + c + 1]       = acc[nf][1];
            hb[(r + 8) * 65 + c]     = acc[nf][2];
            hb[(r + 8) * 65 + c + 1] = acc[nf][3];
        }
    }
    __syncthreads();

    // ---- emit fp32 h ----
    {
        const int r = t >> 1, hc = (t & 1) * 32;
        float* op = g_h32 + ((size_t)(b * Nn) + node0 + r) * 64 + hc;
#pragma unroll
        for (int i = 0; i < 8; i++) {
            const float* s = hb + r * 65 + hc + i * 4;
            *(float4*)(op + i * 4) = make_float4(s[0], s[1], s[2], s[3]);
        }
    }
    // ---- emit node-pair packed bf16 ----
#pragma unroll
    for (int q = 0; q < 16; q++) {
        int idx = t + q * 128;               // 0..2047
        int pr = idx >> 6, j = idx & 63;
        float v0 = hb[(2 * pr) * 65 + j];
        float v1 = hb[(2 * pr + 1) * 65 + j];
        g_hpk_hi[(size_t)b * 131072 + ((node0 >> 1) + pr) * 64 + j] = packbf(v0, v1);
    }
}

// ============================================================================
// Kernel 2 (R11 verbatim): BK=32, 256 thr, warp tile 16x32, cp.async 3-stage,
// one barrier/tile, 4 CTAs/SM.
// ============================================================================
constexpr int A_ROWSTR = 40;                   // floats per A row (32 + 8 pad)
constexpr int A_STAGE  = 64 * A_ROWSTR;        // 2560 u32
constexpr int B_STR    = 72;                   // u32 per B kpair row
constexpr int B_STAGE  = 16 * B_STR;           // 1152 u32
constexpr int STAGES   = 3;
constexpr int OFF_A  = 0;
constexpr int OFF_B  = STAGES * A_STAGE;              // 7680
constexpr int OFF_RS = OFF_B + STAGES * B_STAGE;      // 11136 (64 floats)
constexpr int OFF_RI = OFF_RS + 64;                   // 11200 (64 floats)
constexpr int SMEM_U32 = OFF_RI + 64;                 // 11264
constexpr int SMEM_BYTES = SMEM_U32 * 4;              // 45056

DEV_INLINE void cp16(uint32_t saddr, const void* gptr) {
    asm volatile("cp.async.cg.shared.global [%0], [%1], 16;\n"
                 :: "r"(saddr), "l"(gptr));
}
DEV_INLINE void cp_commit() { asm volatile("cp.async.commit_group;\n"); }
DEV_INLINE void cp_wait1()  { asm volatile("cp.async.wait_group 1;\n"); }
DEV_INLINE void cp_wait0()  { asm volatile("cp.async.wait_group 0;\n"); }

__global__ void __launch_bounds__(256, 4)
spconv_gemm_kernel(const float* __restrict__ adj, const float* __restrict__ bias,
                   float* __restrict__ out)
{
    extern __shared__ unsigned sm[];
    const uint32_t smb = (uint32_t)__cvta_generic_to_shared(sm);

    const int t    = threadIdx.x;
    const int lane = t & 31, warp = t >> 5;
    const int g = lane >> 2, tg = lane & 3;
    const int wrow = warp >> 1, wcol = warp & 1;     // 4 x 2 warp grid
    const int bx = blockIdx.x, b = blockIdx.y;

    // A copy: thread row t>>2 (0..63), 32B chunk t&3 (coalesced)
    const int arow = t >> 2, achk = t & 3;
    const float* adj_base =
        adj + ((size_t)(b * Nn) + (size_t)bx * 64 + arow) * Nn + achk * 8;
    const uint32_t sa_base = smb + (OFF_A + arow * A_ROWSTR + achk * 8) * 4;
    // B copy: kpair = t>>4, 4 u32 columns
    const int bkp = t >> 4, bn4 = (t & 15) * 4;
    const unsigned* hpH = g_hpk_hi + (size_t)b * 131072 + bkp * 64 + bn4;
    const uint32_t sb_base = smb + (OFF_B + bkp * B_STR + bn4) * 4;

    float acc[4][4];
#pragma unroll
    for (int nf = 0; nf < 4; nf++)
#pragma unroll
        for (int i = 0; i < 4; i++) acc[nf][i] = 0.f;

    float rsum0 = 0.f, rsum1 = 0.f;
    const int r0 = wrow * 16 + g;

    auto issue = [&](int kt, int s) {
        const float* ga = adj_base + (size_t)kt * 32;
        uint32_t sa = sa_base + s * (A_STAGE * 4);
        cp16(sa,      ga);
        cp16(sa + 16, ga + 4);
        cp16(sb_base + s * (B_STAGE * 4), hpH + (size_t)kt * 1024);
        cp_commit();
    };

    auto compute = [&](int s) {
        const float*    Af = (const float*)(sm + OFF_A + s * A_STAGE);
        const unsigned* Bh = sm + OFF_B + s * B_STAGE;
#pragma unroll
        for (int ks = 0; ks < 2; ks++) {
            unsigned bh[4][2];
#pragma unroll
            for (int nf = 0; nf < 4; nf++) {
                int n = wcol * 32 + nf * 8 + g;
                int k0 = (ks * 8 + tg) * B_STR + n;
                bh[nf][0] = Bh[k0];  bh[nf][1] = Bh[k0 + 4 * B_STR];
            }
            const int kb = ks * 16 + 2 * tg;
            float2 p0 = *(const float2*)(Af + (r0    ) * A_ROWSTR + kb);
            float2 p1 = *(const float2*)(Af + (r0 + 8) * A_ROWSTR + kb);
            float2 p2 = *(const float2*)(Af + (r0    ) * A_ROWSTR + kb + 8);
            float2 p3 = *(const float2*)(Af + (r0 + 8) * A_ROWSTR + kb + 8);
            if (wcol == 0) {
                rsum0 += (p0.x + p0.y) + (p2.x + p2.y);
                rsum1 += (p1.x + p1.y) + (p3.x + p3.y);
            }
            unsigned ah[4];
            ah[0] = packbf(p0.x, p0.y); ah[1] = packbf(p1.x, p1.y);
            ah[2] = packbf(p2.x, p2.y); ah[3] = packbf(p3.x, p3.y);
#pragma unroll
            for (int nf = 0; nf < 4; nf++)
                mma_bf16(acc[nf], ah, bh[nf]);
        }
    };

    // ---- 3-stage pipeline, one barrier per tile ----
    issue(0, 0);
    issue(1, 1);
    int s = 0, si = 2;
#pragma unroll 1
    for (int kt = 0; kt < 128; kt++) {
        if (kt >= 126) cp_wait0(); else cp_wait1();
        __syncthreads();
        compute(s);
        if (kt + 2 < 128) issue(kt + 2, si);
        else cp_commit();                 // keep group-count semantics in tail
        s  = (s  == STAGES - 1) ? 0 : s + 1;
        si = (si == STAGES - 1) ? 0 : si + 1;
    }

    // ---- rowsum -> rinv ----
    float* rs   = (float*)(sm + OFF_RS);
    float* rinv = (float*)(sm + OFF_RI);
    __syncthreads();
    if (wcol == 0) {
        rsum0 += __shfl_xor_sync(0xffffffffu, rsum0, 1);
        rsum0 += __shfl_xor_sync(0xffffffffu, rsum0, 2);
        rsum1 += __shfl_xor_sync(0xffffffffu, rsum1, 1);
        rsum1 += __shfl_xor_sync(0xffffffffu, rsum1, 2);
        if (tg == 0) { rs[r0] = rsum0; rs[r0 + 8] = rsum1; }
    }
    __syncthreads();
    if (t < 64) rinv[t] = 1.0f / (1.0f + rs[t]);   // +1 = self loop
    __syncthreads();

    // ---- epilogue: out = relu((S + h)*rinv) + bias ----
#pragma unroll
    for (int nf = 0; nf < 4; nf++) {
        int c  = wcol * 32 + nf * 8 + 2 * tg;
        float ri0 = rinv[r0], ri1 = rinv[r0 + 8];
        int gr0 = bx * 64 + r0;
        size_t o0 = ((size_t)(b * Nn + gr0)) * 64 + c;
        size_t o1 = o0 + (size_t)8 * 64;
        float2 h0 = *(const float2*)(g_h32 + o0);
        float2 h1 = *(const float2*)(g_h32 + o1);
        float bz0 = __ldg(bias + c), bz1 = __ldg(bias + c + 1);
        float2 w0, w1;
        w0.x = fmaxf((acc[nf][0] + h0.x) * ri0, 0.f) + bz0;
        w0.y = fmaxf((acc[nf][1] + h0.y) * ri0, 0.f) + bz1;
        w1.x = fmaxf((acc[nf][2] + h1.x) * ri1, 0.f) + bz0;
        w1.y = fmaxf((acc[nf][3] + h1.y) * ri1, 0.f) + bz1;
        *(float2*)(out + o0) = w0;
        *(float2*)(out + o1) = w1;
    }
}

// ============================================================================
extern "C" void kernel_launch(void* const* d_in, const int* in_sizes, int n_in,
                              void* d_out, int out_size)
{
    const float* x    = (const float*)d_in[0];
    const float* adj  = (const float*)d_in[1];
    const float* wgt  = (const float*)d_in[2];
    const float* bias = (const float*)d_in[3];
    float* out = (float*)d_out;

    spconv_h_mma<<<dim3(64, 8), 128>>>(x, wgt);
    spconv_gemm_kernel<<<dim3(64, 8), 256, SMEM_BYTES>>>(adj, bias, out);
}

// round 14
// speedup vs baseline: 1.5222x; 1.0399x over previous
#include <cuda_runtime.h>
#include <cuda_bf16.h>
#include <cstdint>

#define DEV_INLINE __device__ __forceinline__

constexpr int Bb = 8;
constexpr int Nn = 4096;

// ---------------- static device scratch (no allocation) ----------------
__device__ unsigned g_hpk_hi[Bb * (Nn/2) * 64];   // h bf16, node-pair packed (4 MB)

DEV_INLINE unsigned packbf(float a, float b) {
    __nv_bfloat162 t2 = __floats2bfloat162_rn(a, b);
    return *reinterpret_cast<unsigned*>(&t2);
}

DEV_INLINE void mma_bf16(float* c, const unsigned* a, const unsigned* b) {
    asm volatile(
        "mma.sync.aligned.m16n8k16.row.col.f32.bf16.bf16.f32 "
        "{%0,%1,%2,%3}, {%4,%5,%6,%7}, {%8,%9}, {%0,%1,%2,%3};\n"
        : "+f"(c[0]), "+f"(c[1]), "+f"(c[2]), "+f"(c[3])
        : "r"(a[0]), "r"(a[1]), "r"(a[2]), "r"(a[3]), "r"(b[0]), "r"(b[1]));
}

DEV_INLINE void ldsm4(unsigned* r, uint32_t addr) {
    asm volatile(
        "ldmatrix.sync.aligned.m8n8.x4.shared.b16 {%0,%1,%2,%3}, [%4];\n"
        : "=r"(r[0]), "=r"(r[1]), "=r"(r[2]), "=r"(r[3]) : "r"(addr));
}

// bf16 half of a packed pair -> fp32 (exact)
DEV_INLINE float bfhalf(unsigned u, int hi) {
    return __uint_as_float(hi ? (u & 0xffff0000u) : (u << 16));
}

// ============================================================================
// Kernel 1 (mma): h[64-node tile, 64] = x_tile[64,128] @ W[128,64].
// Emits ONLY the bf16 node-pair packed h (fp32 copy no longer needed).
// ============================================================================
constexpr int K1_OFFW = 64 * 68;                // after x tile
constexpr int K1_U32  = K1_OFFW + 64 * 72;      // 8960 u32 = 35.8 KB

__global__ void __launch_bounds__(128)
spconv_h_mma(const float* __restrict__ x, const float* __restrict__ wgt)
{
    __shared__ unsigned sm1[K1_U32];
    const uint32_t smb = (uint32_t)__cvta_generic_to_shared(sm1);
    const int t = threadIdx.x;
    const int lane = t & 31, warp = t >> 5;
    const int g = lane >> 2, tg = lane & 3;
    const int lm_row = lane & 15, lm_kp = ((lane >> 4) & 1) * 4;
    const int b = blockIdx.y;
    const int node0 = blockIdx.x * 64;

    // ---- load x tile -> bf16 pairs (row-major, stride 68 u32) ----
    {
        const int row = t >> 1, hc = t & 1;
        const float* src = x + ((size_t)(b * Nn) + node0 + row) * 128 + hc * 64;
        unsigned* dst = sm1 + row * 68 + hc * 32;
#pragma unroll
        for (int i = 0; i < 16; i++) {
            float4 v = ((const float4*)src)[i];
            dst[2*i]   = packbf(v.x, v.y);
            dst[2*i+1] = packbf(v.z, v.w);
        }
    }
    // ---- load W -> bf16 kpair layout (stride 72 u32) ----
    for (int idx = t; idx < 64 * 64; idx += 128) {
        int kp = idx >> 6, j = idx & 63;
        int ka = kp * 2, m = ka >> 5, a = ka & 31, p = j >> 4, w = j & 15;
        const float* wp = wgt + (((m * 4 + p) * 32 + a) << 4) + w;
        sm1[K1_OFFW + kp * 72 + j] = packbf(wp[0], wp[16]);  // a, a+1
    }
    __syncthreads();

    // ---- mma: warp rows 16*warp..+15, full 64 cols, K=128 ----
    float acc[8][4];
#pragma unroll
    for (int nf = 0; nf < 8; nf++)
#pragma unroll
        for (int i = 0; i < 4; i++) acc[nf][i] = 0.f;

    const uint32_t aBase = smb + ((warp * 16 + lm_row) * 68) * 4;
#pragma unroll
    for (int ks = 0; ks < 8; ks++) {
        unsigned ah[4];
        ldsm4(ah, aBase + (ks * 8 + lm_kp) * 4);
#pragma unroll
        for (int nf = 0; nf < 8; nf++) {
            unsigned bh[2];
            bh[0] = sm1[K1_OFFW + (ks * 8 + tg) * 72 + nf * 8 + g];
            bh[1] = sm1[K1_OFFW + (ks * 8 + 4 + tg) * 72 + nf * 8 + g];
            mma_bf16(acc[nf], ah, bh);
        }
    }
    __syncthreads();                 // x tile no longer needed; reuse as hbuf

    // ---- stage acc -> hbuf[64][65] fp32 ----
    float* hb = (float*)sm1;
    {
        const int r = warp * 16 + g;
#pragma unroll
        for (int nf = 0; nf < 8; nf++) {
            int c = nf * 8 + 2 * tg;
            hb[r * 65 + c]           = acc[nf][0];
            hb[r * 65 + c + 1]       = acc[nf][1];
            hb[(r + 8) * 65 + c]     = acc[nf][2];
            hb[(r + 8) * 65 + c + 1] = acc[nf][3];
        }
    }
    __syncthreads();

    // ---- emit node-pair packed bf16 ----
#pragma unroll
    for (int q = 0; q < 16; q++) {
        int idx = t + q * 128;               // 0..2047
        int pr = idx >> 6, j = idx & 63;
        float v0 = hb[(2 * pr) * 65 + j];
        float v1 = hb[(2 * pr + 1) * 65 + j];
        g_hpk_hi[(size_t)b * 131072 + ((node0 >> 1) + pr) * 64 + j] = packbf(v0, v1);
    }
}

// ============================================================================
// Kernel 2 (R11/R13 skeleton): BK=32, 256 thr, warp tile 16x32, cp.async
// 3-stage + L2::256B prefetch on A, one barrier/tile, 4 CTAs/SM.
// Epilogue self-loop h now read from bf16 g_hpk_hi (L2-hot).
// ============================================================================
constexpr int A_ROWSTR = 40;                   // floats per A row (32 + 8 pad)
constexpr int A_STAGE  = 64 * A_ROWSTR;        // 2560 u32
constexpr int B_STR    = 72;                   // u32 per B kpair row
constexpr int B_STAGE  = 16 * B_STR;           // 1152 u32
constexpr int STAGES   = 3;
constexpr int OFF_A  = 0;
constexpr int OFF_B  = STAGES * A_STAGE;              // 7680
constexpr int OFF_RS = OFF_B + STAGES * B_STAGE;      // 11136 (64 floats)
constexpr int OFF_RI = OFF_RS + 64;                   // 11200 (64 floats)
constexpr int SMEM_U32 = OFF_RI + 64;                 // 11264
constexpr int SMEM_BYTES = SMEM_U32 * 4;              // 45056

DEV_INLINE void cp16pf(uint32_t saddr, const void* gptr) {   // +256B L2 prefetch
    asm volatile("cp.async.cg.shared.global.L2::256B [%0], [%1], 16;\n"
                 :: "r"(saddr), "l"(gptr));
}
DEV_INLINE void cp16(uint32_t saddr, const void* gptr) {
    asm volatile("cp.async.cg.shared.global [%0], [%1], 16;\n"
                 :: "r"(saddr), "l"(gptr));
}
DEV_INLINE void cp_commit() { asm volatile("cp.async.commit_group;\n"); }
DEV_INLINE void cp_wait1()  { asm volatile("cp.async.wait_group 1;\n"); }
DEV_INLINE void cp_wait0()  { asm volatile("cp.async.wait_group 0;\n"); }

__global__ void __launch_bounds__(256, 4)
spconv_gemm_kernel(const float* __restrict__ adj, const float* __restrict__ bias,
                   float* __restrict__ out)
{
    extern __shared__ unsigned sm[];
    const uint32_t smb = (uint32_t)__cvta_generic_to_shared(sm);

    const int t    = threadIdx.x;
    const int lane = t & 31, warp = t >> 5;
    const int g = lane >> 2, tg = lane & 3;
    const int wrow = warp >> 1, wcol = warp & 1;     // 4 x 2 warp grid
    const int bx = blockIdx.x, b = blockIdx.y;

    // A copy: thread row t>>2 (0..63), 32B chunk t&3 (coalesced)
    const int arow = t >> 2, achk = t & 3;
    const float* adj_base =
        adj + ((size_t)(b * Nn) + (size_t)bx * 64 + arow) * Nn + achk * 8;
    const uint32_t sa_base = smb + (OFF_A + arow * A_ROWSTR + achk * 8) * 4;
    // B copy: kpair = t>>4, 4 u32 columns
    const int bkp = t >> 4, bn4 = (t & 15) * 4;
    const unsigned* hpH = g_hpk_hi + (size_t)b * 131072 + bkp * 64 + bn4;
    const uint32_t sb_base = smb + (OFF_B + bkp * B_STR + bn4) * 4;

    float acc[4][4];
#pragma unroll
    for (int nf = 0; nf < 4; nf++)
#pragma unroll
        for (int i = 0; i < 4; i++) acc[nf][i] = 0.f;

    float rsum0 = 0.f, rsum1 = 0.f;
    const int r0 = wrow * 16 + g;

    auto issue = [&](int kt, int s) {
        const float* ga = adj_base + (size_t)kt * 32;
        uint32_t sa = sa_base + s * (A_STAGE * 4);
        cp16pf(sa,      ga);
        cp16pf(sa + 16, ga + 4);
        cp16(sb_base + s * (B_STAGE * 4), hpH + (size_t)kt * 1024);
        cp_commit();
    };

    auto compute = [&](int s) {
        const float*    Af = (const float*)(sm + OFF_A + s * A_STAGE);
        const unsigned* Bh = sm + OFF_B + s * B_STAGE;
#pragma unroll
        for (int ks = 0; ks < 2; ks++) {
            unsigned bh[4][2];
#pragma unroll
            for (int nf = 0; nf < 4; nf++) {
                int n = wcol * 32 + nf * 8 + g;
                int k0 = (ks * 8 + tg) * B_STR + n;
                bh[nf][0] = Bh[k0];  bh[nf][1] = Bh[k0 + 4 * B_STR];
            }
            const int kb = ks * 16 + 2 * tg;
            float2 p0 = *(const float2*)(Af + (r0    ) * A_ROWSTR + kb);
            float2 p1 = *(const float2*)(Af + (r0 + 8) * A_ROWSTR + kb);
            float2 p2 = *(const float2*)(Af + (r0    ) * A_ROWSTR + kb + 8);
            float2 p3 = *(const float2*)(Af + (r0 + 8) * A_ROWSTR + kb + 8);
            if (wcol == 0) {
                rsum0 += (p0.x + p0.y) + (p2.x + p2.y);
                rsum1 += (p1.x + p1.y) + (p3.x + p3.y);
            }
            unsigned ah[4];
            ah[0] = packbf(p0.x, p0.y); ah[1] = packbf(p1.x, p1.y);
            ah[2] = packbf(p2.x, p2.y); ah[3] = packbf(p3.x, p3.y);
#pragma unroll
            for (int nf = 0; nf < 4; nf++)
                mma_bf16(acc[nf], ah, bh[nf]);
        }
    };

    // ---- 3-stage pipeline, one barrier per tile ----
    issue(0, 0);
    issue(1, 1);
    int s = 0, si = 2;
#pragma unroll 1
    for (int kt = 0; kt < 128; kt++) {
        if (kt >= 126) cp_wait0(); else cp_wait1();
        __syncthreads();
        compute(s);
        if (kt + 2 < 128) issue(kt + 2, si);
        else cp_commit();                 // keep group-count semantics in tail
        s  = (s  == STAGES - 1) ? 0 : s + 1;
        si = (si == STAGES - 1) ? 0 : si + 1;
    }

    // ---- rowsum -> rinv ----
    float* rs   = (float*)(sm + OFF_RS);
    float* rinv = (float*)(sm + OFF_RI);
    __syncthreads();
    if (wcol == 0) {
        rsum0 += __shfl_xor_sync(0xffffffffu, rsum0, 1);
        rsum0 += __shfl_xor_sync(0xffffffffu, rsum0, 2);
        rsum1 += __shfl_xor_sync(0xffffffffu, rsum1, 1);
        rsum1 += __shfl_xor_sync(0xffffffffu, rsum1, 2);
        if (tg == 0) { rs[r0] = rsum0; rs[r0 + 8] = rsum1; }
    }
    __syncthreads();
    if (t < 64) rinv[t] = 1.0f / (1.0f + rs[t]);   // +1 = self loop
    __syncthreads();

    // ---- epilogue: out = relu((S + h)*rinv) + bias; h from bf16 pairs ----
    const unsigned* hB = g_hpk_hi + (size_t)b * 131072;
    const int gr0 = bx * 64 + r0;
    const int pr0 = gr0 >> 1;          // bx*64 even -> parity = r0&1 = g&1
    const int par = g & 1;
#pragma unroll
    for (int nf = 0; nf < 4; nf++) {
        int c  = wcol * 32 + nf * 8 + 2 * tg;
        float ri0 = rinv[r0], ri1 = rinv[r0 + 8];
        uint2 hv0 = *(const uint2*)(hB + pr0 * 64 + c);
        uint2 hv1 = *(const uint2*)(hB + (pr0 + 4) * 64 + c);
        size_t o0 = ((size_t)(b * Nn + gr0)) * 64 + c;
        size_t o1 = o0 + (size_t)8 * 64;
        float bz0 = __ldg(bias + c), bz1 = __ldg(bias + c + 1);
        float2 w0, w1;
        w0.x = fmaxf((acc[nf][0] + bfhalf(hv0.x, par)) * ri0, 0.f) + bz0;
        w0.y = fmaxf((acc[nf][1] + bfhalf(hv0.y, par)) * ri0, 0.f) + bz1;
        w1.x = fmaxf((acc[nf][2] + bfhalf(hv1.x, par)) * ri1, 0.f) + bz0;
        w1.y = fmaxf((acc[nf][3] + bfhalf(hv1.y, par)) * ri1, 0.f) + bz1;
        *(float2*)(out + o0) = w0;
        *(float2*)(out + o1) = w1;
    }
}

// ============================================================================
extern "C" void kernel_launch(void* const* d_in, const int* in_sizes, int n_in,
                              void* d_out, int out_size)
{
    const float* x    = (const float*)d_in[0];
    const float* adj  = (const float*)d_in[1];
    const float* wgt  = (const float*)d_in[2];
    const float* bias = (const float*)d_in[3];
    float* out = (float*)d_out;

    spconv_h_mma<<<dim3(64, 8), 128>>>(x, wgt);
    spconv_gemm_kernel<<<dim3(64, 8), 256, SMEM_BYTES>>>(adj, bias, out);
}